// round 6
// baseline (speedup 1.0000x reference)
#include <cuda_runtime.h>

#define D  512
#define TT 128
#define NN 64
#define SS 128

// ---- scratch (static device globals; no allocation) ----
__device__ float g_P[8192 * 512];        // dec @ W_obj[0:512] + b_obj
__device__ float g_qproj[384 * 512];     // src_e[0:6] @ W_obj[1024:1536]
__device__ float g_embproj[6 * 512];     // emb @ W_obj[512:1024]
__device__ float g_embdir[6 * 5];        // emb @ W_dir[512:1024]
__device__ float g_qdir[384 * 5];        // src_e[0:6] @ W_dir[1024:1536]
__device__ float g_rdir[384 * 5];        // src_e[0:6] @ W_dir[1536:2048]

// ============================================================
// GEMM tile worker: C[bm:bm+128, bn:bn+128] = A[.,512] @ B[512,512] (+bias)
// 256 threads, 8x8 per thread, K-tile 16. sm must hold 4224 floats.
// ============================================================
__device__ __forceinline__ void gemm_tile(const float* __restrict__ A,
                                          const float* __restrict__ B,
                                          float* __restrict__ C,
                                          const float* __restrict__ bias,
                                          int bm, int bn, float* sm) {
    float (*As)[132] = (float(*)[132])sm;
    float (*Bs)[132] = (float(*)[132])(sm + 16 * 132);
    const int tid = threadIdx.x;
    const int tx = tid & 15, ty = tid >> 4;

    const int a_row = tid >> 1;
    const int a_kk  = (tid & 1) * 8;
    const int b_kk  = tid >> 4;
    const int b_col = (tid & 15) * 8;

    float acc[8][8];
    #pragma unroll
    for (int i = 0; i < 8; i++)
        #pragma unroll
        for (int j = 0; j < 8; j++) acc[i][j] = 0.f;

    const float* aBase = A + (size_t)(bm + a_row) * D + a_kk;
    const float* bBase = B + (size_t)b_kk * D + bn + b_col;

    for (int k0 = 0; k0 < D; k0 += 16) {
        float4 av0 = *(const float4*)(aBase + k0);
        float4 av1 = *(const float4*)(aBase + k0 + 4);
        float4 bv0 = *(const float4*)(bBase + (size_t)k0 * D);
        float4 bv1 = *(const float4*)(bBase + (size_t)k0 * D + 4);
        As[a_kk + 0][a_row] = av0.x; As[a_kk + 1][a_row] = av0.y;
        As[a_kk + 2][a_row] = av0.z; As[a_kk + 3][a_row] = av0.w;
        As[a_kk + 4][a_row] = av1.x; As[a_kk + 5][a_row] = av1.y;
        As[a_kk + 6][a_row] = av1.z; As[a_kk + 7][a_row] = av1.w;
        *(float4*)&Bs[b_kk][b_col]     = bv0;
        *(float4*)&Bs[b_kk][b_col + 4] = bv1;
        __syncthreads();
        #pragma unroll
        for (int kk = 0; kk < 16; kk++) {
            float ra[8], rb[8];
            #pragma unroll
            for (int i = 0; i < 8; i++) ra[i] = As[kk][ty * 8 + i];
            #pragma unroll
            for (int j = 0; j < 8; j++) rb[j] = Bs[kk][tx * 8 + j];
            #pragma unroll
            for (int i = 0; i < 8; i++)
                #pragma unroll
                for (int j = 0; j < 8; j++) acc[i][j] += ra[i] * rb[j];
        }
        __syncthreads();
    }

    #pragma unroll
    for (int i = 0; i < 8; i++) {
        int r = bm + ty * 8 + i;
        float* cp = C + (size_t)r * D + bn + tx * 8;
        if (bias) {
            const float* bp = bias + bn + tx * 8;
            #pragma unroll
            for (int j = 0; j < 8; j++) cp[j] = acc[i][j] + bp[j];
        } else {
            #pragma unroll
            for (int j = 0; j < 8; j++) cp[j] = acc[i][j];
        }
    }
}

// ============================================================
// Stage 1 mega-kernel: 466 blocks x 256 threads
//   [0,256)   : g_P = dec @ W_obj[0:512] + b_obj
//   [256,268) : g_qproj = src_e[0:6] @ W_obj[1024:1536]
//   [268,274) : embproj (+ embdir)
//   [274,466) : srcdir (2 rows per block)
// ============================================================
__global__ __launch_bounds__(256) void stage1_k(const float* __restrict__ dec,
                                                const float* __restrict__ srcE,
                                                const float* __restrict__ emb,
                                                const float* __restrict__ Wo,
                                                const float* __restrict__ bo,
                                                const float* __restrict__ Wdir) {
    __shared__ __align__(16) float sm[4224];
    const int bid = blockIdx.x;
    const int tid = threadIdx.x;

    if (bid < 256) {
        gemm_tile(dec, Wo, g_P, bo, (bid >> 2) * 128, (bid & 3) * 128, sm);
    } else if (bid < 268) {
        int q = bid - 256;
        gemm_tile(srcE, Wo + (size_t)2 * D * D, g_qproj, (const float*)0,
                  (q >> 2) * 128, (q & 3) * 128, sm);
    } else if (bid < 274) {
        int i = bid - 268;
        float* e = sm;
        e[tid]       = emb[i * D + tid];
        e[tid + 256] = emb[i * D + tid + 256];
        __syncthreads();
        #pragma unroll
        for (int half = 0; half < 2; half++) {
            int c = tid + half * 256;
            float acc = 0.f;
            const float* wb = Wo + (size_t)D * D + c;
            #pragma unroll 8
            for (int k = 0; k < D; k++) acc += e[k] * wb[(size_t)k * D];
            g_embproj[i * D + c] = acc;
        }
        if (tid < 5) {
            float a = 0.f;
            const float* wd = Wdir + (size_t)D * 5 + tid;
            for (int k = 0; k < D; k++) a += e[k] * wd[k * 5];
            g_embdir[i * 5 + tid] = a;
        }
    } else {
        const int g  = tid >> 7;
        const int lt = tid & 127;
        const int r  = (bid - 274) * 2 + g;
        float acc[10];
        #pragma unroll
        for (int j = 0; j < 10; j++) acc[j] = 0.f;
        const float* row = srcE + (size_t)r * D;
        for (int k = lt; k < D; k += 128) {
            float v = row[k];
            const float* w2 = Wdir + (size_t)(2 * D + k) * 5;
            const float* w3 = Wdir + (size_t)(3 * D + k) * 5;
            #pragma unroll
            for (int j = 0; j < 5; j++) {
                acc[j]     += v * w2[j];
                acc[5 + j] += v * w3[j];
            }
        }
        #pragma unroll
        for (int off = 16; off; off >>= 1)
            #pragma unroll
            for (int j = 0; j < 10; j++)
                acc[j] += __shfl_down_sync(0xffffffffu, acc[j], off);
        float* red = sm;
        const int w = tid >> 5, lane = tid & 31;
        if (lane == 0)
            #pragma unroll
            for (int j = 0; j < 10; j++) red[w * 10 + j] = acc[j];
        __syncthreads();
        if (lt < 10) {
            int wb = g * 4;
            float s = red[(wb + 0) * 10 + lt] + red[(wb + 1) * 10 + lt]
                    + red[(wb + 2) * 10 + lt] + red[(wb + 3) * 10 + lt];
            if (lt < 5) g_qdir[r * 5 + lt] = s;
            else        g_rdir[r * 5 + (lt - 5)] = s;
        }
    }
}

// ============================================================
// Stage 2 kernel: 296 blocks x 256 threads
//   [0,256)   : einsum, 32-row t-tiles (4 per n). bids b and b+148 land on
//               the same SM (LUT_classic[bid%148]) -> SMs LUT[0..107] get
//               TWO co-resident einsum blocks (16 warps: latency cross-hiding)
//   [256,296) : typedir, 205 rows/block, lands on LUT[108..147] (the 40 SMs
//               that have only one einsum block)
// ============================================================
__global__ __launch_bounds__(256, 2) void stage2_k(const float* __restrict__ srcE,
                                                   const unsigned char* __restrict__ mask,
                                                   const int* __restrict__ tgt,
                                                   const float* __restrict__ dec,
                                                   const float* __restrict__ Wt,
                                                   const float* __restrict__ bt,
                                                   const float* __restrict__ Wd,
                                                   const float* __restrict__ bd,
                                                   float* __restrict__ out_type,
                                                   float* __restrict__ out_obj,
                                                   float* __restrict__ out_dir) {
    __shared__ __align__(16) float sm[5760];
    const int bid = blockIdx.x;
    const int tid = threadIdx.x;

    if (bid < 256) {
        // einsum('snd,tnd->tns') for one n, 32 t-rows, double-buffered
        float (*As)[16][36]  = (float(*)[16][36])sm;                 // 2 x 16 x 36
        float (*Bs)[16][132] = (float(*)[16][132])(sm + 2 * 16 * 36);
        const int n  = bid >> 2;
        const int t0 = (bid & 3) * 32;
        const int tx = tid & 31;        // s / 4
        const int ty = tid >> 5;        // t / 4  (0..7)  -- constant per warp

        // A loaders: tid < 128 -> 32 rows x 16 k
        const int a_row = tid >> 2;          // 0..31
        const int a_kk  = (tid & 3) * 4;
        // B loaders: all -> 128 rows x 16 k
        const int b_row = tid >> 1;          // 0..127
        const int b_kk  = (tid & 1) * 8;

        const float *aBase = 0, *epBase = 0, *qpBase = 0;
        if (tid < 128) {
            const int t  = t0 + a_row;
            const int tp = (t + 1) & (TT - 1);
            const int* tg = tgt + ((size_t)tp * NN + n) * 3;
            aBase  = g_P + ((size_t)t * NN + n) * D + a_kk;
            epBase = g_embproj + (size_t)tg[0] * D + a_kk;
            qpBase = g_qproj + ((size_t)tg[1] * NN + n) * D + a_kk;
        }
        const float* bBase = srcE + ((size_t)b_row * NN + n) * D + b_kk;

        float acc[4][4];
        #pragma unroll
        for (int i = 0; i < 4; i++)
            #pragma unroll
            for (int j = 0; j < 4; j++) acc[i][j] = 0.f;

        // prologue -> buffer 0
        {
            if (tid < 128) {
                float4 av = *(const float4*)(aBase);
                float4 ev = *(const float4*)(epBase);
                float4 qv = *(const float4*)(qpBase);
                As[0][a_kk + 0][a_row] = (av.x + ev.x) + qv.x;
                As[0][a_kk + 1][a_row] = (av.y + ev.y) + qv.y;
                As[0][a_kk + 2][a_row] = (av.z + ev.z) + qv.z;
                As[0][a_kk + 3][a_row] = (av.w + ev.w) + qv.w;
            }
            float4 bv0 = *(const float4*)(bBase);
            float4 bv1 = *(const float4*)(bBase + 4);
            Bs[0][b_kk + 0][b_row] = bv0.x; Bs[0][b_kk + 1][b_row] = bv0.y;
            Bs[0][b_kk + 2][b_row] = bv0.z; Bs[0][b_kk + 3][b_row] = bv0.w;
            Bs[0][b_kk + 4][b_row] = bv1.x; Bs[0][b_kk + 5][b_row] = bv1.y;
            Bs[0][b_kk + 6][b_row] = bv1.z; Bs[0][b_kk + 7][b_row] = bv1.w;
        }
        __syncthreads();

        const int NT = D / 16;   // 32
        for (int kt = 0; kt < NT; kt++) {
            float4 av, ev, qv, bv0, bv1;
            const bool more = (kt + 1 < NT);
            if (more) {
                int k0 = (kt + 1) * 16;
                if (tid < 128) {
                    av = *(const float4*)(aBase + k0);
                    ev = *(const float4*)(epBase + k0);
                    qv = *(const float4*)(qpBase + k0);
                }
                bv0 = *(const float4*)(bBase + k0);
                bv1 = *(const float4*)(bBase + k0 + 4);
            }
            const int cb = kt & 1;
            #pragma unroll
            for (int kk = 0; kk < 16; kk++) {
                float4 ra = *(const float4*)&As[cb][kk][ty * 4];   // warp broadcast
                float4 rb = *(const float4*)&Bs[cb][kk][tx * 4];
                float fa[4] = {ra.x, ra.y, ra.z, ra.w};
                float fb[4] = {rb.x, rb.y, rb.z, rb.w};
                #pragma unroll
                for (int i = 0; i < 4; i++)
                    #pragma unroll
                    for (int j = 0; j < 4; j++) acc[i][j] += fa[i] * fb[j];
            }
            if (more) {
                const int nb = cb ^ 1;
                if (tid < 128) {
                    As[nb][a_kk + 0][a_row] = (av.x + ev.x) + qv.x;
                    As[nb][a_kk + 1][a_row] = (av.y + ev.y) + qv.y;
                    As[nb][a_kk + 2][a_row] = (av.z + ev.z) + qv.z;
                    As[nb][a_kk + 3][a_row] = (av.w + ev.w) + qv.w;
                }
                Bs[nb][b_kk + 0][b_row] = bv0.x; Bs[nb][b_kk + 1][b_row] = bv0.y;
                Bs[nb][b_kk + 2][b_row] = bv0.z; Bs[nb][b_kk + 3][b_row] = bv0.w;
                Bs[nb][b_kk + 4][b_row] = bv1.x; Bs[nb][b_kk + 5][b_row] = bv1.y;
                Bs[nb][b_kk + 6][b_row] = bv1.z; Bs[nb][b_kk + 7][b_row] = bv1.w;
                __syncthreads();
            }
        }

        #pragma unroll
        for (int i = 0; i < 4; i++) {
            int tt = t0 + ty * 4 + i;
            float* op = out_obj + ((size_t)tt * NN + n) * SS + tx * 4;
            #pragma unroll
            for (int j = 0; j < 4; j++) {
                int s = tx * 4 + j;
                op[j] = mask[n * SS + s] ? -__int_as_float(0x7f800000) : acc[i][j];
            }
        }
    } else {
        // typedir: 205 rows per block (40 blocks cover 8192 rows)
        float* sW = sm;                                    // 512 x 11
        for (int i = tid; i < D * 6; i += 256) {
            int k = i / 6, c = i % 6;
            sW[k * 11 + c] = Wt[i];
        }
        for (int i = tid; i < D * 5; i += 256) {
            int k = i / 5, c = i % 5;
            sW[k * 11 + 6 + c] = Wd[i];
        }
        __syncthreads();

        const int w = tid >> 5, lane = tid & 31;
        const int r0   = (bid - 256) * 205;
        int rend = r0 + 205;
        if (rend > 8192) rend = 8192;

        for (int r = r0 + w; r < rend; r += 8) {
            const float* drow = dec + (size_t)r * D;
            float acc[11];
            #pragma unroll
            for (int c = 0; c < 11; c++) acc[c] = 0.f;
            #pragma unroll 4
            for (int u = 0; u < 16; u++) {
                int k = u * 32 + lane;
                float v = drow[k];
                const float* wp = &sW[k * 11];
                #pragma unroll
                for (int c = 0; c < 11; c++) acc[c] += v * wp[c];
            }
            #pragma unroll
            for (int off = 16; off; off >>= 1)
                #pragma unroll
                for (int c = 0; c < 11; c++)
                    acc[c] += __shfl_xor_sync(0xffffffffu, acc[c], off);
            if (lane < 11) {
                int t = r >> 6, n = r & 63;
                int tp = (t + 1) & (TT - 1);
                const int* tg = tgt + ((size_t)tp * NN + n) * 3;
                if (lane < 6) {
                    out_type[(size_t)r * 6 + lane] = acc[lane] + bt[lane];
                } else {
                    int j = lane - 6;
                    out_dir[(size_t)r * 5 + j] = acc[lane] + bd[j]
                        + g_embdir[tg[0] * 5 + j]
                        + g_qdir[((size_t)tg[1] * NN + n) * 5 + j]
                        + g_rdir[((size_t)tg[2] * NN + n) * 5 + j];
                }
            }
        }
    }
}

// ============================================================
extern "C" void kernel_launch(void* const* d_in, const int* in_sizes, int n_in,
                              void* d_out, int out_size) {
    const float*         dec  = (const float*)d_in[0];   // (T,N,D)
    const int*           tgt  = (const int*)d_in[1];     // (T,N,3)
    const float*         srcE = (const float*)d_in[2];   // (S,N,D)
    const unsigned char* mask = (const unsigned char*)d_in[3]; // (N,S) bool
    const float*         emb  = (const float*)d_in[4];   // (6,D)
    const float*         Wt   = (const float*)d_in[5];   // (D,6)
    const float*         bt   = (const float*)d_in[6];   // (6,)
    const float*         Wo   = (const float*)d_in[7];   // (3D,D)
    const float*         bo   = (const float*)d_in[8];   // (D,)
    const float*         Wd   = (const float*)d_in[9];   // (4D,5)
    const float*         bd   = (const float*)d_in[10];  // (5,)

    float* out       = (float*)d_out;
    float* out_type  = out;                                   // (T,N,6)
    float* out_obj   = out + (size_t)TT * NN * 6;             // (T,N,S)
    float* out_dir   = out + (size_t)TT * NN * 6 + (size_t)TT * NN * SS; // (T,N,5)

    stage1_k<<<466, 256>>>(dec, srcE, emb, Wo, bo, Wd);
    stage2_k<<<296, 256>>>(srcE, mask, tgt, dec, Wt, bt, Wd, bd,
                           out_type, out_obj, out_dir);
}

// round 8
// speedup vs baseline: 2.1243x; 2.1243x over previous
#include <cuda_runtime.h>
#include <cuda_bf16.h>
#include <cstdint>

#define D  512
#define TT 128
#define NN 64
#define SS 128

// ---- scratch (static device globals; no allocation) ----
__device__ float g_P[8192 * 512];        // dec @ W0 + b_obj
__device__ float g_qproj[384 * 512];     // src_e[0:6] @ W_obj[1024:1536]
__device__ float g_embproj[6 * 512];
__device__ float g_embdir[6 * 5];
__device__ float g_qdir[384 * 5];
__device__ float g_rdir[384 * 5];

// ================= warp-level tensor helpers (sm_80+ base-target) =================
__device__ __forceinline__ uint32_t smem_u32(const void* p) {
    uint32_t a;
    asm("{ .reg .u64 t; cvta.to.shared.u64 t, %1; cvt.u32.u64 %0, t; }" : "=r"(a) : "l"(p));
    return a;
}
__device__ __forceinline__ void ldsm_x4(uint32_t* r, uint32_t addr) {
    asm volatile("ldmatrix.sync.aligned.m8n8.x4.shared.b16 {%0,%1,%2,%3}, [%4];"
                 : "=r"(r[0]), "=r"(r[1]), "=r"(r[2]), "=r"(r[3]) : "r"(addr));
}
__device__ __forceinline__ void ldsm_x2(uint32_t* r, uint32_t addr) {
    asm volatile("ldmatrix.sync.aligned.m8n8.x2.shared.b16 {%0,%1}, [%2];"
                 : "=r"(r[0]), "=r"(r[1]) : "r"(addr));
}
__device__ __forceinline__ void ldsm_x2_t(uint32_t* r, uint32_t addr) {
    asm volatile("ldmatrix.sync.aligned.m8n8.x2.trans.shared.b16 {%0,%1}, [%2];"
                 : "=r"(r[0]), "=r"(r[1]) : "r"(addr));
}
__device__ __forceinline__ void mma16816(float* c, const uint32_t* a, const uint32_t* b) {
    asm volatile("mma.sync.aligned.m16n8k16.row.col.f32.bf16.bf16.f32 "
                 "{%0,%1,%2,%3}, {%4,%5,%6,%7}, {%8,%9}, {%0,%1,%2,%3};"
                 : "+f"(c[0]), "+f"(c[1]), "+f"(c[2]), "+f"(c[3])
                 : "r"(a[0]), "r"(a[1]), "r"(a[2]), "r"(a[3]), "r"(b[0]), "r"(b[1]));
}

// ---- fp32x8 (regs) -> bf16 hi/lo x8, stored as one uint4 each ----
__device__ __forceinline__ void split_sts8(const float* xs, char* dhi, char* dlo) {
    uint32_t hw[4], lw[4];
    #pragma unroll
    for (int p = 0; p < 4; p++) {
        float a = xs[2 * p], b = xs[2 * p + 1];
        __nv_bfloat162 hb2 = __floats2bfloat162_rn(a, b);
        float ha = __bfloat162float(__low2bfloat16(hb2));
        float hbv = __bfloat162float(__high2bfloat16(hb2));
        hw[p] = *(uint32_t*)&hb2;
        __nv_bfloat162 lb2 = __floats2bfloat162_rn(a - ha, b - hbv);
        lw[p] = *(uint32_t*)&lb2;
    }
    *(uint4*)dhi = make_uint4(hw[0], hw[1], hw[2], hw[3]);
    *(uint4*)dlo = make_uint4(lw[0], lw[1], lw[2], lw[3]);
}
__device__ __forceinline__ void load8(float* d, const float* s) {
    float4 u = *(const float4*)s, v = *(const float4*)(s + 4);
    d[0] = u.x; d[1] = u.y; d[2] = u.z; d[3] = u.w;
    d[4] = v.x; d[5] = v.y; d[6] = v.z; d[7] = v.w;
}

// smem layout constants
#define A_LD_B   48      // 16 bf16 + pad -> 48 bytes/row
#define A_PLANE  (128 * A_LD_B)        // 6144
#define B1_LD_B  272     // 128 bf16 + pad -> 272 bytes/row (K-major W tile)
#define B1_PLANE (16 * B1_LD_B)        // 4352
#define B2_PLANE (128 * A_LD_B)        // 6144 (N-major E tile)
#define SMEM_BYTES 24832

// ================= mm core 1: C[128,128] = A[bm:,512] @ W[512, bn:] (+bias) =================
// A row-major [r][512] fp32; W K-major [k][512] fp32. 3-term bf16 split via HMMA.
__device__ __forceinline__ void mm_core1(const float* __restrict__ A,
                                         const float* __restrict__ W,
                                         float* __restrict__ C,
                                         const float* __restrict__ bias,
                                         int bm, int bn, char* smem) {
    const int tid = threadIdx.x, lane = tid & 31, wid = tid >> 5;
    const int wm = wid >> 2, wn = wid & 3;
    char* aHi = smem;                 char* aLo = smem + A_PLANE;
    char* bHi = smem + 2 * A_PLANE;   char* bLo = bHi + B1_PLANE;
    const uint32_t aHiU = smem_u32(aHi), aLoU = aHiU + A_PLANE;
    const uint32_t bHiU = aHiU + 2 * A_PLANE, bLoU = bHiU + B1_PLANE;

    const int arow = tid >> 1, ah = (tid & 1) * 8;
    const int bk = tid >> 4, bn8 = (tid & 15) * 8;
    const float* aSrc = A + (size_t)(bm + arow) * 512 + ah;
    const float* bSrc = W + (size_t)bk * 512 + bn + bn8;

    float acc[4][4][4];
    #pragma unroll
    for (int mt = 0; mt < 4; mt++)
        #pragma unroll
        for (int nt = 0; nt < 4; nt++)
            #pragma unroll
            for (int cc = 0; cc < 4; cc++) acc[mt][nt][cc] = 0.f;

    float pa[8], pb[8];
    load8(pa, aSrc);
    load8(pb, bSrc);

    for (int kt = 0; kt < 32; kt++) {
        split_sts8(pa, aHi + arow * A_LD_B + ah * 2, aLo + arow * A_LD_B + ah * 2);
        split_sts8(pb, bHi + bk * B1_LD_B + bn8 * 2, bLo + bk * B1_LD_B + bn8 * 2);
        __syncthreads();
        if (kt < 31) {
            load8(pa, aSrc + (kt + 1) * 16);
            load8(pb, bSrc + (size_t)(kt + 1) * 16 * 512);
        }
        uint32_t bfh[4][2], bfl[4][2];
        #pragma unroll
        for (int nt = 0; nt < 4; nt++) {
            uint32_t off = (lane & 15) * B1_LD_B + (wn * 32 + nt * 8) * 2;
            ldsm_x2_t(bfh[nt], bHiU + off);
            ldsm_x2_t(bfl[nt], bLoU + off);
        }
        #pragma unroll
        for (int mt = 0; mt < 4; mt++) {
            uint32_t aoff = (wm * 64 + mt * 16 + (lane & 15)) * A_LD_B + (lane >> 4) * 16;
            uint32_t fh[4], fl[4];
            ldsm_x4(fh, aHiU + aoff);
            ldsm_x4(fl, aLoU + aoff);
            #pragma unroll
            for (int nt = 0; nt < 4; nt++) {
                mma16816(acc[mt][nt], fh, bfh[nt]);
                mma16816(acc[mt][nt], fh, bfl[nt]);
                mma16816(acc[mt][nt], fl, bfh[nt]);
            }
        }
        __syncthreads();
    }

    #pragma unroll
    for (int mt = 0; mt < 4; mt++) {
        #pragma unroll
        for (int nt = 0; nt < 4; nt++) {
            int row = bm + wm * 64 + mt * 16 + (lane >> 2);
            int col = bn + wn * 32 + nt * 8 + 2 * (lane & 3);
            float b0 = bias ? bias[col] : 0.f;
            float b1 = bias ? bias[col + 1] : 0.f;
            float* c0 = C + (size_t)row * 512 + col;
            c0[0] = acc[mt][nt][0] + b0;
            c0[1] = acc[mt][nt][1] + b1;
            float* c1 = C + (size_t)(row + 8) * 512 + col;
            c1[0] = acc[mt][nt][2] + b0;
            c1[1] = acc[mt][nt][3] + b1;
        }
    }
}

// ================= mm core 2: einsum tile for one n =================
// C[t][s] = sum_d (P[t,n,d]+embproj[tg0,d]+qproj[tg1,n,d]) * srcE[s,n,d]
__device__ __forceinline__ void mm_core2(const int* __restrict__ tgt,
                                         const float* __restrict__ srcE,
                                         const unsigned char* __restrict__ mask,
                                         float* __restrict__ out_obj,
                                         int n, char* smem) {
    const int tid = threadIdx.x, lane = tid & 31, wid = tid >> 5;
    const int wm = wid >> 2, wn = wid & 3;
    char* aHi = smem;                 char* aLo = smem + A_PLANE;
    char* bHi = smem + 2 * A_PLANE;   char* bLo = bHi + B2_PLANE;
    const uint32_t aHiU = smem_u32(aHi), aLoU = aHiU + A_PLANE;
    const uint32_t bHiU = aHiU + 2 * A_PLANE, bLoU = bHiU + B2_PLANE;

    const int arow = tid >> 1, ah = (tid & 1) * 8;
    const int tp = (arow + 1) & (TT - 1);
    const int* tg = tgt + ((size_t)tp * NN + n) * 3;
    const float* pA = g_P + ((size_t)arow * NN + n) * 512 + ah;
    const float* pE = g_embproj + (size_t)tg[0] * 512 + ah;
    const float* pQ = g_qproj + ((size_t)tg[1] * NN + n) * 512 + ah;
    const float* pB = srcE + ((size_t)arow * NN + n) * 512 + ah;  // brow == arow

    float acc[4][4][4];
    #pragma unroll
    for (int mt = 0; mt < 4; mt++)
        #pragma unroll
        for (int nt = 0; nt < 4; nt++)
            #pragma unroll
            for (int cc = 0; cc < 4; cc++) acc[mt][nt][cc] = 0.f;

    float pa[8], pb[8];
    {
        float xa[8], xe[8], xq[8];
        load8(xa, pA); load8(xe, pE); load8(xq, pQ);
        #pragma unroll
        for (int i = 0; i < 8; i++) pa[i] = (xa[i] + xe[i]) + xq[i];
        load8(pb, pB);
    }

    for (int kt = 0; kt < 32; kt++) {
        split_sts8(pa, aHi + arow * A_LD_B + ah * 2, aLo + arow * A_LD_B + ah * 2);
        split_sts8(pb, bHi + arow * A_LD_B + ah * 2, bLo + arow * A_LD_B + ah * 2);
        __syncthreads();
        if (kt < 31) {
            int k0 = (kt + 1) * 16;
            float xa[8], xe[8], xq[8];
            load8(xa, pA + k0); load8(xe, pE + k0); load8(xq, pQ + k0);
            #pragma unroll
            for (int i = 0; i < 8; i++) pa[i] = (xa[i] + xe[i]) + xq[i];
            load8(pb, pB + k0);
        }
        uint32_t bfh[4][2], bfl[4][2];
        #pragma unroll
        for (int nt = 0; nt < 4; nt++) {
            uint32_t off = (wn * 32 + nt * 8 + (lane & 7)) * A_LD_B + ((lane >> 3) & 1) * 16;
            ldsm_x2(bfh[nt], bHiU + off);
            ldsm_x2(bfl[nt], bLoU + off);
        }
        #pragma unroll
        for (int mt = 0; mt < 4; mt++) {
            uint32_t aoff = (wm * 64 + mt * 16 + (lane & 15)) * A_LD_B + (lane >> 4) * 16;
            uint32_t fh[4], fl[4];
            ldsm_x4(fh, aHiU + aoff);
            ldsm_x4(fl, aLoU + aoff);
            #pragma unroll
            for (int nt = 0; nt < 4; nt++) {
                mma16816(acc[mt][nt], fh, bfh[nt]);
                mma16816(acc[mt][nt], fh, bfl[nt]);
                mma16816(acc[mt][nt], fl, bfh[nt]);
            }
        }
        __syncthreads();
    }

    const float NEG_INF = __int_as_float(0xff800000);
    #pragma unroll
    for (int mt = 0; mt < 4; mt++) {
        #pragma unroll
        for (int nt = 0; nt < 4; nt++) {
            int t = wm * 64 + mt * 16 + (lane >> 2);
            int s = wn * 32 + nt * 8 + 2 * (lane & 3);
            unsigned char m0 = mask[n * SS + s], m1 = mask[n * SS + s + 1];
            float* o0 = out_obj + ((size_t)t * NN + n) * SS + s;
            o0[0] = m0 ? NEG_INF : acc[mt][nt][0];
            o0[1] = m1 ? NEG_INF : acc[mt][nt][1];
            float* o1 = out_obj + ((size_t)(t + 8) * NN + n) * SS + s;
            o1[0] = m0 ? NEG_INF : acc[mt][nt][2];
            o1[1] = m1 ? NEG_INF : acc[mt][nt][3];
        }
    }
}

// ================= k1: 466 blocks =================
//  [0,256)   g_P = dec @ W0 + b_obj      (HMMA)
//  [256,268) g_qproj = srcE[0:384] @ W2  (HMMA)
//  [268,274) embproj + embdir
//  [274,466) srcdir
__global__ __launch_bounds__(256, 2) void k1(const float* __restrict__ dec,
                                             const float* __restrict__ srcE,
                                             const float* __restrict__ emb,
                                             const float* __restrict__ Wo,
                                             const float* __restrict__ bo,
                                             const float* __restrict__ Wd) {
    __shared__ __align__(16) char smem[SMEM_BYTES];
    const int bid = blockIdx.x, tid = threadIdx.x;

    if (bid < 256) {
        mm_core1(dec, Wo, g_P, bo, (bid >> 2) * 128, (bid & 3) * 128, smem);
    } else if (bid < 268) {
        int q = bid - 256;
        mm_core1(srcE, Wo + (size_t)2 * D * D, g_qproj, (const float*)0,
                 (q >> 2) * 128, (q & 3) * 128, smem);
    } else if (bid < 274) {
        int i = bid - 268;
        float* e = (float*)smem;
        e[tid]       = emb[i * D + tid];
        e[tid + 256] = emb[i * D + tid + 256];
        __syncthreads();
        #pragma unroll
        for (int half = 0; half < 2; half++) {
            int c = tid + half * 256;
            float acc = 0.f;
            const float* wb = Wo + (size_t)D * D + c;
            #pragma unroll 8
            for (int k = 0; k < D; k++) acc += e[k] * wb[(size_t)k * D];
            g_embproj[i * D + c] = acc;
        }
        if (tid < 5) {
            float a = 0.f;
            const float* wd = Wd + (size_t)D * 5 + tid;
            for (int k = 0; k < D; k++) a += e[k] * wd[k * 5];
            g_embdir[i * 5 + tid] = a;
        }
    } else {
        const int g  = tid >> 7;
        const int lt = tid & 127;
        const int r  = (bid - 274) * 2 + g;
        float acc[10];
        #pragma unroll
        for (int j = 0; j < 10; j++) acc[j] = 0.f;
        const float* row = srcE + (size_t)r * D;
        for (int k = lt; k < D; k += 128) {
            float v = row[k];
            const float* w2 = Wd + (size_t)(2 * D + k) * 5;
            const float* w3 = Wd + (size_t)(3 * D + k) * 5;
            #pragma unroll
            for (int j = 0; j < 5; j++) {
                acc[j]     += v * w2[j];
                acc[5 + j] += v * w3[j];
            }
        }
        #pragma unroll
        for (int off = 16; off; off >>= 1)
            #pragma unroll
            for (int j = 0; j < 10; j++)
                acc[j] += __shfl_down_sync(0xffffffffu, acc[j], off);
        float* red = (float*)smem;
        const int w = tid >> 5, lane = tid & 31;
        if (lane == 0)
            #pragma unroll
            for (int j = 0; j < 10; j++) red[w * 10 + j] = acc[j];
        __syncthreads();
        if (lt < 10) {
            int wb = g * 4;
            float s = red[(wb + 0) * 10 + lt] + red[(wb + 1) * 10 + lt]
                    + red[(wb + 2) * 10 + lt] + red[(wb + 3) * 10 + lt];
            if (lt < 5) g_qdir[r * 5 + lt] = s;
            else        g_rdir[r * 5 + (lt - 5)] = s;
        }
    }
}

// ================= k2: 104 blocks =================
//  [0,64)   einsum per n (HMMA, fused gather at stage time)
//  [64,104) typedir (205 rows each)
__global__ __launch_bounds__(256, 2) void k2(const float* __restrict__ srcE,
                                             const unsigned char* __restrict__ mask,
                                             const int* __restrict__ tgt,
                                             const float* __restrict__ dec,
                                             const float* __restrict__ Wt,
                                             const float* __restrict__ bt,
                                             const float* __restrict__ Wd,
                                             const float* __restrict__ bd,
                                             float* __restrict__ out_type,
                                             float* __restrict__ out_obj,
                                             float* __restrict__ out_dir) {
    __shared__ __align__(16) char smem[SMEM_BYTES];
    const int bid = blockIdx.x, tid = threadIdx.x;

    if (bid < 64) {
        mm_core2(tgt, srcE, mask, out_obj, bid, smem);
    } else {
        float* sW = (float*)smem;                          // 512 x 11
        for (int i = tid; i < D * 6; i += 256) {
            int k = i / 6, c = i % 6;
            sW[k * 11 + c] = Wt[i];
        }
        for (int i = tid; i < D * 5; i += 256) {
            int k = i / 5, c = i % 5;
            sW[k * 11 + 6 + c] = Wd[i];
        }
        __syncthreads();
        const int w = tid >> 5, lane = tid & 31;
        const int r0 = (bid - 64) * 205;
        int rend = r0 + 205;
        if (rend > 8192) rend = 8192;
        for (int r = r0 + w; r < rend; r += 8) {
            const float* drow = dec + (size_t)r * D;
            float acc[11];
            #pragma unroll
            for (int c = 0; c < 11; c++) acc[c] = 0.f;
            #pragma unroll 4
            for (int u = 0; u < 16; u++) {
                int k = u * 32 + lane;
                float v = drow[k];
                const float* wp = &sW[k * 11];
                #pragma unroll
                for (int c = 0; c < 11; c++) acc[c] += v * wp[c];
            }
            #pragma unroll
            for (int off = 16; off; off >>= 1)
                #pragma unroll
                for (int c = 0; c < 11; c++)
                    acc[c] += __shfl_xor_sync(0xffffffffu, acc[c], off);
            if (lane < 11) {
                int t = r >> 6, n = r & 63;
                int tp = (t + 1) & (TT - 1);
                const int* tg = tgt + ((size_t)tp * NN + n) * 3;
                if (lane < 6) {
                    out_type[(size_t)r * 6 + lane] = acc[lane] + bt[lane];
                } else {
                    int j = lane - 6;
                    out_dir[(size_t)r * 5 + j] = acc[lane] + bd[j]
                        + g_embdir[tg[0] * 5 + j]
                        + g_qdir[((size_t)tg[1] * NN + n) * 5 + j]
                        + g_rdir[((size_t)tg[2] * NN + n) * 5 + j];
                }
            }
        }
    }
}

// ================= launch =================
extern "C" void kernel_launch(void* const* d_in, const int* in_sizes, int n_in,
                              void* d_out, int out_size) {
    const float*         dec  = (const float*)d_in[0];   // (T,N,D)
    const int*           tgt  = (const int*)d_in[1];     // (T,N,3)
    const float*         srcE = (const float*)d_in[2];   // (S,N,D)
    const unsigned char* mask = (const unsigned char*)d_in[3]; // (N,S) bool
    const float*         emb  = (const float*)d_in[4];   // (6,D)
    const float*         Wt   = (const float*)d_in[5];   // (D,6)
    const float*         bt   = (const float*)d_in[6];   // (6,)
    const float*         Wo   = (const float*)d_in[7];   // (3D,D)
    const float*         bo   = (const float*)d_in[8];   // (D,)
    const float*         Wd   = (const float*)d_in[9];   // (4D,5)
    const float*         bd   = (const float*)d_in[10];  // (5,)

    float* out      = (float*)d_out;
    float* out_type = out;                                    // (T,N,6)
    float* out_obj  = out + (size_t)TT * NN * 6;              // (T,N,S)
    float* out_dir  = out + (size_t)TT * NN * 6 + (size_t)TT * NN * SS; // (T,N,5)

    k1<<<466, 256>>>(dec, srcE, emb, Wo, bo, Wd);
    k2<<<104, 256>>>(srcE, mask, tgt, dec, Wt, bt, Wd, bd,
                     out_type, out_obj, out_dir);
}